// round 4
// baseline (speedup 1.0000x reference)
#include <cuda_runtime.h>
#include <math.h>

#define BB 64
#define QQ 4096
#define NN 256
#define NC 20          // foreground classes
#define NL 21          // logits per query (NC + 1)
#define QT 16          // q-tile per block
#define RPT 4          // rows per thread  (QT / 4 row-groups)

#define COST_CLASS  1.0f
#define COST_CENTER 5.0f
#define COST_IOU    2.0f
#define INF_REPLACE 1000000.0f
// Gate on the EXPANDED-form d^2 (|p|^2 - 2 p.t + |t|^2) with a conservative
// margin: magnitudes < ~1.5e4 so rounding error < ~1e-2; anything with
// expanded d^2 > 4.0625 is provably truly > 4 => center cost inf => 1e6.
// Borderline elements take the exact path that matches reference arithmetic.
#define THR_FAST    4.0625f

__global__ __launch_bounds__(256) void matcher_kernel(
    const float* __restrict__ logits,    // [B, Q, 21]
    const float* __restrict__ pboxes,    // [B, Q, 6]
    const int*   __restrict__ labels,    // [B, N]
    const float* __restrict__ tboxes,    // [B, N, 6]
    float*       __restrict__ out)       // [B, Q, N]
{
    const int blocks_per_b = QQ / QT;            // 256
    const int b  = blockIdx.x / blocks_per_b;
    const int q0 = (blockIdx.x % blocks_per_b) * QT;
    const int t  = threadIdx.x;
    const int tgroup = t >> 6;                   // 0..3 : row group
    const int n4     = t & 63;                   // target quad (n = 4*n4..4*n4+3)

    __shared__ float  s_lg[QT * NL];
    __shared__ float  s_probs[QT][NC];
    __shared__ float4 s_pcn[QT];                 // (pcx,pcy,pcz,|pc|^2)
    __shared__ float4 s_ps[QT];                  // (psx,psy,psz,vol1)

    // ---- per-thread target constants (register-resident all block) ----
    float Ax[4], Ay[4], Az[4], Kk[4];            // -2*tc, |tc|^2
    {
        const float* tb = tboxes + ((size_t)b * NN + 4 * n4) * 6;
        #pragma unroll
        for (int j = 0; j < 4; j++) {
            float x = __ldg(tb + j*6 + 0);
            float y = __ldg(tb + j*6 + 1);
            float z = __ldg(tb + j*6 + 2);
            Ax[j] = -2.0f * x; Ay[j] = -2.0f * y; Az[j] = -2.0f * z;
            Kk[j] = x*x + y*y + z*z;
        }
    }

    // ---- stage logits (coalesced) + pred boxes ----
    {
        const float* lg = logits + ((size_t)b * QQ + q0) * NL;
        for (int i = t; i < QT * NL; i += 256) s_lg[i] = lg[i];
    }
    if (t < QT) {
        const float* pb = pboxes + ((size_t)b * QQ + q0 + t) * 6;
        float x  = pb[0], y  = pb[1], z  = pb[2];
        float sx = pb[3], sy = pb[4], sz = pb[5];
        s_pcn[t] = make_float4(x, y, z, x*x + y*y + z*z);
        s_ps[t]  = make_float4(sx, sy, sz, sx*sy*sz);
    }
    __syncthreads();

    // ---- softmax: one thread per q ----
    if (t < QT) {
        float e[NL]; float s = 0.0f;
        #pragma unroll
        for (int c = 0; c < NL; c++) { e[c] = expf(s_lg[t*NL + c]); s += e[c]; }
        float inv = 1.0f / s;
        #pragma unroll
        for (int c = 0; c < NC; c++) s_probs[t][c] = e[c] * inv;
    }
    __syncthreads();

    // ---- main loop: RPT rows per thread, one STG.128 per row ----
    float4* orow = (float4*)(out + (((size_t)b * QQ + q0 + tgroup * RPT) * NN)) + n4;

    #pragma unroll
    for (int u = 0; u < RPT; u++) {
        const int qi = tgroup * RPT + u;
        const float4 p  = s_pcn[qi];
        const float  tq = THR_FAST - p.w;        // near iff m_j <= tq

        const float m0 = fmaf(Ax[0], p.x, fmaf(Ay[0], p.y, fmaf(Az[0], p.z, Kk[0])));
        const float m1 = fmaf(Ax[1], p.x, fmaf(Ay[1], p.y, fmaf(Az[1], p.z, Kk[1])));
        const float m2 = fmaf(Ax[2], p.x, fmaf(Ay[2], p.y, fmaf(Az[2], p.z, Kk[2])));
        const float m3 = fmaf(Ax[3], p.x, fmaf(Ay[3], p.y, fmaf(Az[3], p.z, Kk[3])));

        const bool near = (m0 <= tq) | (m1 <= tq) | (m2 <= tq) | (m3 <= tq);

        float r0 = INF_REPLACE, r1 = INF_REPLACE, r2 = INF_REPLACE, r3 = INF_REPLACE;

        if (__any_sync(0xFFFFFFFFu, near)) {     // warp-uniform, rare (~3%)
            if (near) {
                const float mm[4] = {m0, m1, m2, m3};
                float rv[4] = {INF_REPLACE, INF_REPLACE, INF_REPLACE, INF_REPLACE};
                const float4 ps = s_ps[qi];
                #pragma unroll
                for (int j = 0; j < 4; j++) {
                    if (mm[j] > tq) continue;
                    // exact reference arithmetic
                    const float tcx = -0.5f * Ax[j];
                    const float tcy = -0.5f * Ay[j];
                    const float tcz = -0.5f * Az[j];
                    const float dx = p.x - tcx, dy = p.y - tcy, dz = p.z - tcz;
                    const float d2 = dx*dx + dy*dy + dz*dz;
                    const float dist = sqrtf(d2);
                    if (dist > 2.0f) continue;

                    const int nn = 4 * n4 + j;
                    const float* tbj = tboxes + ((size_t)b * NN + nn) * 6;
                    const float tsx = __ldg(tbj + 3);
                    const float tsy = __ldg(tbj + 4);
                    const float tsz = __ldg(tbj + 5);

                    float ix = fminf(p.x + 0.5f*ps.x, tcx + 0.5f*tsx)
                             - fmaxf(p.x - 0.5f*ps.x, tcx - 0.5f*tsx);
                    float iy = fminf(p.y + 0.5f*ps.y, tcy + 0.5f*tsy)
                             - fmaxf(p.y - 0.5f*ps.y, tcy - 0.5f*tsy);
                    float iz = fminf(p.z + 0.5f*ps.z, tcz + 0.5f*tsz)
                             - fmaxf(p.z - 0.5f*ps.z, tcz - 0.5f*tsz);
                    ix = fmaxf(ix, 0.0f); iy = fmaxf(iy, 0.0f); iz = fmaxf(iz, 0.0f);

                    const float inter = ix * iy * iz;
                    const float vol2  = tsx * tsy * tsz;
                    const float uni   = ps.w + vol2 - inter;
                    const float iou   = (uni > 0.0f) ? (inter / uni) : 0.0f;

                    const int   lbl = __ldg(labels + b * NN + nn);
                    const float cls = -s_probs[qi][lbl];
                    rv[j] = COST_CLASS * cls + COST_CENTER * dist + COST_IOU * (1.0f - iou);
                }
                r0 = rv[0]; r1 = rv[1]; r2 = rv[2]; r3 = rv[3];
            }
        }
        orow[(size_t)u * (NN / 4)] = make_float4(r0, r1, r2, r3);
    }
}

extern "C" void kernel_launch(void* const* d_in, const int* in_sizes, int n_in,
                              void* d_out, int out_size)
{
    const float* logits = (const float*)d_in[0];  // [B,Q,21]
    const float* pboxes = (const float*)d_in[1];  // [B,Q,6]
    const int*   labels = (const int*)  d_in[2];  // [B,N]
    const float* tboxes = (const float*)d_in[3];  // [B,N,6]
    float*       out    = (float*)d_out;          // [B,Q,N]

    dim3 grid(BB * (QQ / QT));
    dim3 block(256);
    matcher_kernel<<<grid, block>>>(logits, pboxes, labels, tboxes, out);
}

// round 5
// speedup vs baseline: 1.3542x; 1.3542x over previous
#include <cuda_runtime.h>
#include <math.h>

#define BB 64
#define QQ 4096
#define NN 256
#define NC 20
#define NL 21
#define QCH 512              // q rows per block
#define INF_REPLACE 1000000.0f
// Conservative gate on expanded d^2 = |p|^2 - 2 p.t + |t|^2. Magnitudes are
// <= ~1.5e4 so fp32 rounding error < ~1e-2; margin 1/16 guarantees any pair
// with true d^2 <= 4 is flagged. Flagged elements are re-decided with the
// exact reference arithmetic (dist = sqrt(sum((p-t)^2)) <= 2).
#define THR_FAST 4.0625f

// Exact per-element cost, reference arithmetic. Rare (~0.03% of elements).
__device__ __noinline__ float exact_cost(
    const float* __restrict__ logits, const int* __restrict__ labels,
    const float* __restrict__ tboxes,
    int b, int q, int n,
    float pcx, float pcy, float pcz,
    float psx, float psy, float psz)
{
    const float* tb = tboxes + ((size_t)b * NN + n) * 6;
    const float tcx = __ldg(tb + 0), tcy = __ldg(tb + 1), tcz = __ldg(tb + 2);
    const float dx = pcx - tcx, dy = pcy - tcy, dz = pcz - tcz;
    const float d2 = dx*dx + dy*dy + dz*dz;
    const float dist = sqrtf(d2);
    if (dist > 2.0f) return INF_REPLACE;

    const float tsx = __ldg(tb + 3), tsy = __ldg(tb + 4), tsz = __ldg(tb + 5);
    float ix = fminf(pcx + 0.5f*psx, tcx + 0.5f*tsx) - fmaxf(pcx - 0.5f*psx, tcx - 0.5f*tsx);
    float iy = fminf(pcy + 0.5f*psy, tcy + 0.5f*tsy) - fmaxf(pcy - 0.5f*psy, tcy - 0.5f*tsy);
    float iz = fminf(pcz + 0.5f*psz, tcz + 0.5f*tsz) - fmaxf(pcz - 0.5f*psz, tcz - 0.5f*tsz);
    ix = fmaxf(ix, 0.0f); iy = fmaxf(iy, 0.0f); iz = fmaxf(iz, 0.0f);
    const float inter = ix * iy * iz;
    const float vol1 = psx * psy * psz;
    const float vol2 = tsx * tsy * tsz;
    const float uni  = vol1 + vol2 - inter;
    const float iou  = (uni > 0.0f) ? (inter / uni) : 0.0f;

    const float* lg = logits + ((size_t)b * QQ + q) * NL;
    const int lbl = __ldg(labels + b * NN + n);
    float s = 0.0f, el = 0.0f;
    #pragma unroll
    for (int c = 0; c < NL; c++) {
        float e = expf(__ldg(lg + c));
        s += e;
        if (c == lbl) el = e;
    }
    const float inv = 1.0f / s;
    const float cls = -(el * inv);
    return cls + 5.0f * dist + 2.0f * (1.0f - iou);
}

__global__ __launch_bounds__(256, 5) void matcher_kernel(
    const float* __restrict__ logits,    // [B, Q, 21]
    const float* __restrict__ pboxes,    // [B, Q, 6]
    const int*   __restrict__ labels,    // [B, N]
    const float* __restrict__ tboxes,    // [B, N, 6]
    float*       __restrict__ out)       // [B, Q, N]
{
    const int b  = blockIdx.y;
    const int q0 = blockIdx.x * QCH;
    const int t  = threadIdx.x;

    __shared__ float  s_praw[QCH * 6];   // raw pred boxes (sizes kept for slow path)
    __shared__ float4 s_p[QCH];          // (pcx, pcy, pcz, tq = THR - |pc|^2)
    __shared__ float4 s_tA[NN];          // (-2tcx, -2tcy, -2tcz, |tc|^2)
    __shared__ int    s_flag[QCH];       // row has at least one near pair

    // ---- stage: pred boxes (coalesced), target gate constants, flags ----
    {
        const float* pb = pboxes + ((size_t)b * QQ + q0) * 6;
        #pragma unroll
        for (int i = t; i < QCH * 6; i += 256) s_praw[i] = pb[i];
    }
    {
        const float* tb = tboxes + ((size_t)b * NN + t) * 6;
        const float x = __ldg(tb + 0), y = __ldg(tb + 1), z = __ldg(tb + 2);
        s_tA[t] = make_float4(-2.0f * x, -2.0f * y, -2.0f * z, x*x + y*y + z*z);
    }
    s_flag[t] = 0;
    s_flag[t + 256] = 0;
    __syncthreads();

    #pragma unroll
    for (int qi = t; qi < QCH; qi += 256) {
        const float x = s_praw[qi*6+0], y = s_praw[qi*6+1], z = s_praw[qi*6+2];
        s_p[qi] = make_float4(x, y, z, THR_FAST - (x*x + y*y + z*z));
    }
    __syncthreads();

    // ---- Phase A: gate. thread t owns target t, sweeps all rows ----
    {
        const float4 A = s_tA[t];
        const int lane0 = ((t & 31) == 0);
        #pragma unroll 4
        for (int qi = 0; qi < QCH; qi++) {
            const float4 p = s_p[qi];
            const float m = fmaf(A.x, p.x, fmaf(A.y, p.y, fmaf(A.z, p.z, A.w)));
            const bool near = (m <= p.w);
            if (__any_sync(0xFFFFFFFFu, near)) {
                if (lane0) s_flag[qi] = 1;     // benign race, same value
            }
        }
    }
    __syncthreads();

    // ---- Phase B: stream stores. thread t writes float4 column t of each 4-row group ----
    float4* base4 = (float4*)(out + ((size_t)b * QQ + q0) * NN);
    const int g   = t >> 6;          // row sub-offset 0..3
    const int c4  = t & 63;          // float4 column -> targets 4*c4 .. 4*c4+3
    const float4 vinf = make_float4(INF_REPLACE, INF_REPLACE, INF_REPLACE, INF_REPLACE);

    #pragma unroll 4
    for (int k = 0; k < QCH / 4; k++) {
        const int row = (k << 2) + g;          // warp-uniform
        float4 v = vinf;
        if (s_flag[row]) {                     // warp-uniform branch, rare
            const float4 p = s_p[row];
            const float psx = s_praw[row*6+3], psy = s_praw[row*6+4], psz = s_praw[row*6+5];
            const int q = q0 + row;
            #pragma unroll
            for (int j = 0; j < 4; j++) {
                const float4 A = s_tA[4*c4 + j];
                const float m = fmaf(A.x, p.x, fmaf(A.y, p.y, fmaf(A.z, p.z, A.w)));
                if (m <= p.w) {
                    const float r = exact_cost(logits, labels, tboxes,
                                               b, q, 4*c4 + j,
                                               p.x, p.y, p.z, psx, psy, psz);
                    if (j == 0) v.x = r; else if (j == 1) v.y = r;
                    else if (j == 2) v.z = r; else v.w = r;
                }
            }
        }
        base4[(size_t)k * 256 + t] = v;
    }
}

extern "C" void kernel_launch(void* const* d_in, const int* in_sizes, int n_in,
                              void* d_out, int out_size)
{
    const float* logits = (const float*)d_in[0];  // [B,Q,21]
    const float* pboxes = (const float*)d_in[1];  // [B,Q,6]
    const int*   labels = (const int*)  d_in[2];  // [B,N]
    const float* tboxes = (const float*)d_in[3];  // [B,N,6]
    float*       out    = (float*)d_out;          // [B,Q,N]

    dim3 grid(QQ / QCH, BB);                      // (8, 64)
    dim3 block(256);
    matcher_kernel<<<grid, block>>>(logits, pboxes, labels, tboxes, out);
}